// round 6
// baseline (speedup 1.0000x reference)
#include <cuda_runtime.h>
#include <cuda_fp16.h>
#include <cstdint>

#define BB 4
#define CC 64
#define C8 8
#define NN 9216          // 96*96
#define TN 256           // queries per CTA
#define TM 64            // key/value chunk
#define NCHUNK (NN/TM)   // 144
#define KST 72           // Ks row stride (floats)
#define VST 80           // Vs row stride (halfs)

// ---------------- scratch ----------------
__device__ float  g_Qn[(size_t)BB * NN * C8];          // [b][n][k] tf32, pre-halved
__device__ float  g_Kp[(size_t)BB * NCHUNK * C8 * TM]; // [b][ch][k][m] tf32
__device__ __half g_Vp[(size_t)BB * NCHUNK * CC * TM]; // [b][ch][c][m'] f16, m perm within 16
__device__ float  g_vsum[BB * CC];                     // 0.5 * sum_m V_f16[b][c][m]
__device__ float  g_avg[BB * CC];
__device__ float  g_mx [BB * CC];

__device__ __forceinline__ float to_tf32(float v) {
    asm("cvt.rna.tf32.f32 %0, %0;" : "+f"(v));
    return v;
}
__device__ __forceinline__ float th(float x) {      // MUFU.TANH
    asm("tanh.approx.f32 %0, %0;" : "+f"(x));
    return x;
}
__device__ __forceinline__ uint32_t pk(float lo, float hi) {  // f16x2 {lo,hi}
    uint32_t r;
    asm("cvt.rn.f16x2.f32 %0, %1, %2;" : "=r"(r) : "f"(hi), "f"(lo));
    return r;
}
__device__ __forceinline__ uint32_t fb(float v) { return __float_as_uint(v); }
__device__ __forceinline__ uint32_t smem_u32(const void* p) {
    uint32_t a;
    asm("{ .reg .u64 t; cvta.to.shared.u64 t, %1; cvt.u32.u64 %0, t; }" : "=r"(a) : "l"(p));
    return a;
}

__device__ __forceinline__ void mma8(float d[4], const uint32_t a[4], uint32_t b0, uint32_t b1) {
    asm volatile(
        "mma.sync.aligned.m16n8k8.row.col.f32.tf32.tf32.f32 "
        "{%0,%1,%2,%3}, {%4,%5,%6,%7}, {%8,%9}, {%0,%1,%2,%3};"
        : "+f"(d[0]), "+f"(d[1]), "+f"(d[2]), "+f"(d[3])
        : "r"(a[0]), "r"(a[1]), "r"(a[2]), "r"(a[3]), "r"(b0), "r"(b1));
}
__device__ __forceinline__ void mma16(float d[4], const uint32_t a[4], uint32_t b0, uint32_t b1) {
    asm volatile(
        "mma.sync.aligned.m16n8k16.row.col.f32.f16.f16.f32 "
        "{%0,%1,%2,%3}, {%4,%5,%6,%7}, {%8,%9}, {%0,%1,%2,%3};"
        : "+f"(d[0]), "+f"(d[1]), "+f"(d[2]), "+f"(d[3])
        : "r"(a[0]), "r"(a[1]), "r"(a[2]), "r"(a[3]), "r"(b0), "r"(b1));
}

#define CP16(dst, src) \
    asm volatile("cp.async.cg.shared.global [%0], [%1], 16;" :: "r"(dst), "l"(src))
#define CP_COMMIT() asm volatile("cp.async.commit_group;" ::: "memory")
#define CP_WAIT0()  asm volatile("cp.async.wait_group 0;" ::: "memory")

// SMEM byte offsets within dynamic smem
#define SOFF_K 0
#define SOFF_V 4608                         // 2*8*72*4
#define SM_STAGE_END (SOFF_V + 2*CC*VST*2)  // 25088
#define SMEM_BYTES 67584                    // max(stage, 16*32*33*4 reduction)

// ---------------- kernel 1: fused 1x1-conv Q/K/V (Q pre-halved) ----------------
__global__ __launch_bounds__(256) void qkv_kernel(
    const float* __restrict__ x,
    const float* __restrict__ wq, const float* __restrict__ bq,
    const float* __restrict__ wk, const float* __restrict__ bk,
    const float* __restrict__ wv, const float* __restrict__ bv)
{
    __shared__ float sw[80 * 64];
    __shared__ float sb[80];
    int tid = threadIdx.x;
    for (int i = tid; i < 512;  i += 256) sw[i] = wq[i];
    for (int i = tid; i < 512;  i += 256) sw[512 + i] = wk[i];
    for (int i = tid; i < 4096; i += 256) sw[1024 + i] = wv[i];
    if (tid < 80) sb[tid] = (tid < 8) ? bq[tid] : (tid < 16 ? bk[tid - 8] : bv[tid - 16]);
    __syncthreads();

    int n = blockIdx.x * 256 + tid;
    int b = blockIdx.y;
    const float* xb = x + (size_t)b * CC * NN + n;
    float xr[CC];
    #pragma unroll
    for (int c = 0; c < CC; c++) xr[c] = xb[(size_t)c * NN];

    const int ch = n >> 6;
    const int m  = n & 63;
    const int P = (m & 15) >> 1;
    const int mphys = (m & ~15) | ((((P & 3) * 2 + (P >> 2)) << 1) | (m & 1));

    float* qrow  = g_Qn + ((size_t)b * NN + n) * C8;
    float* ktile = g_Kp + ((size_t)(b * NCHUNK + ch) * C8) * TM;
    #pragma unroll 1
    for (int o = 0; o < C8; o++) {
        float aq = sb[o], ak = sb[8 + o];
        const float* wqr = sw + o * 64;
        const float* wkr = sw + 512 + o * 64;
        #pragma unroll
        for (int c = 0; c < CC; c++) { aq += wqr[c] * xr[c]; ak += wkr[c] * xr[c]; }
        qrow[o] = to_tf32(0.5f * aq);      // fold sigmoid's /2 into Q
        ktile[o * TM + m] = to_tf32(ak);
    }
    __half* vtile = g_Vp + ((size_t)(b * NCHUNK + ch) * CC) * TM;
    #pragma unroll 1
    for (int o = 0; o < CC; o++) {
        float av = sb[16 + o];
        const float* wvr = sw + 1024 + o * 64;
        #pragma unroll
        for (int c = 0; c < CC; c++) av += wvr[c] * xr[c];
        vtile[o * TM + mphys] = __float2half_rn(av);
    }
}

// ---------------- kernel 1b: vsum[b][c] = 0.5 * sum_m V_f16 ----------------
__global__ __launch_bounds__(256) void vsum_kernel()
{
    __shared__ float ss[256];
    int bc = blockIdx.x;           // b*64 + c
    int b = bc >> 6, c = bc & 63;
    const __half* vb = g_Vp + (size_t)b * NCHUNK * CC * TM + (size_t)c * TM;
    float s = 0.f;
    for (int i = threadIdx.x; i < NCHUNK * TM; i += 256) {
        int ch = i >> 6, m = i & 63;
        s += __half2float(vb[(size_t)ch * CC * TM + m]);
    }
    ss[threadIdx.x] = s;
    __syncthreads();
    for (int o = 128; o > 0; o >>= 1) {
        if (threadIdx.x < o) ss[threadIdx.x] += ss[threadIdx.x + o];
        __syncthreads();
    }
    if (threadIdx.x == 0) g_vsum[bc] = 0.5f * ss[0];
}

// ---------------- kernel 2: fused tanh-attention, m-split warps ----------------
// 16 warps: nw = wid&7 -> 32 query rows; mh = wid>>3 -> m-half of 32.
// out = 0.5*sum(tanh*V) + vsum + x ; cross-warp m-reduction via SMEM at end.
__global__ __launch_bounds__(512, 1) void attn_mma_kernel(
    const float* __restrict__ x, float* __restrict__ out)
{
    extern __shared__ char sh[];
    float  (*Ks)[C8 * KST] = (float (*)[C8 * KST])(sh + SOFF_K);
    __half (*Vs)[CC * VST] = (__half (*)[CC * VST])(sh + SOFF_V);
    const uint32_t ksb = smem_u32(sh) + SOFF_K;
    const uint32_t vsb = smem_u32(sh) + SOFF_V;

    const int tid = threadIdx.x, wid = tid >> 5, lid = tid & 31;
    const int g = lid >> 2, t = lid & 3;
    const int b = blockIdx.y, n0 = blockIdx.x * TN;
    const int nw = wid & 7, mh = wid >> 3;

    // Q A-fragments (persistent), 2 n-frags of 16 rows
    uint32_t qa[2][4];
    #pragma unroll
    for (int nf = 0; nf < 2; nf++) {
        const float* q0 = g_Qn + ((size_t)b * NN + n0 + nw * 32 + nf * 16 + g) * C8;
        qa[nf][0] = fb(q0[t]);
        qa[nf][1] = fb(q0[8 * C8 + t]);
        qa[nf][2] = fb(q0[t + 4]);
        qa[nf][3] = fb(q0[8 * C8 + t + 4]);
    }

    float acc[2][8][4];
    #pragma unroll
    for (int nf = 0; nf < 2; nf++)
        #pragma unroll
        for (int j = 0; j < 8; j++)
            #pragma unroll
            for (int k = 0; k < 4; k++) acc[nf][j][k] = 0.0f;

    const float*  kbase = g_Kp + (size_t)b * NCHUNK * C8 * TM;
    const __half* vbase = g_Vp + (size_t)b * NCHUNK * CC * TM;

    auto stage = [&](int ch, int p) {
        if (tid < 128) {
            int k = tid >> 4, seg = tid & 15;
            CP16(ksb + (uint32_t)(p * C8 * KST * 4 + k * (KST * 4) + seg * 16),
                 (const char*)(kbase + (size_t)ch * C8 * TM + k * TM) + seg * 16);
        }
        {
            int c = tid >> 3, seg = tid & 7;
            CP16(vsb + (uint32_t)(p * CC * VST * 2 + c * (VST * 2) + seg * 16),
                 (const char*)(vbase + (size_t)ch * CC * TM + c * TM) + seg * 16);
        }
    };

    stage(0, 0);
    CP_COMMIT();

    for (int ch = 0; ch < NCHUNK; ch++) {
        const int p = ch & 1;
        CP_WAIT0();
        __syncthreads();
        if (ch + 1 < NCHUNK) { stage(ch + 1, p ^ 1); CP_COMMIT(); }

        // K B-fragments for this warp's m-half (hoisted, reused across nf)
        uint32_t kb0[4], kb1[4];
        #pragma unroll
        for (int mt = 0; mt < 4; mt++) {
            kb0[mt] = fb(Ks[p][t * KST + mh * 32 + mt * 8 + g]);
            kb1[mt] = fb(Ks[p][(t + 4) * KST + mh * 32 + mt * 8 + g]);
        }

        // GEMM1 + tanh -> f16x2 A-fragments (per nf to bound live registers)
        uint32_t af[2][2][4];
        #pragma unroll
        for (int nf = 0; nf < 2; nf++) {
            float e[4][4];
            #pragma unroll
            for (int mt = 0; mt < 4; mt++) {
                e[mt][0] = e[mt][1] = e[mt][2] = e[mt][3] = 0.0f;
                mma8(e[mt], qa[nf], kb0[mt], kb1[mt]);
            }
            #pragma unroll
            for (int ks = 0; ks < 2; ks++) {
                af[nf][ks][0] = pk(th(e[2 * ks][0]),     th(e[2 * ks][1]));
                af[nf][ks][1] = pk(th(e[2 * ks][2]),     th(e[2 * ks][3]));
                af[nf][ks][2] = pk(th(e[2 * ks + 1][0]), th(e[2 * ks + 1][1]));
                af[nf][ks][3] = pk(th(e[2 * ks + 1][2]), th(e[2 * ks + 1][3]));
            }
        }

        // GEMM2: each B-fragment feeds both n-frags
        #pragma unroll
        for (int ks = 0; ks < 2; ks++) {
            #pragma unroll
            for (int j = 0; j < 8; j++) {
                uint2 bv = *(const uint2*)(&Vs[p][(8 * j + g) * VST + mh * 32 + ks * 16 + 4 * t]);
                mma16(acc[0][j], af[0][ks], bv.x, bv.y);
                mma16(acc[1][j], af[1][ks], bv.x, bv.y);
            }
        }
    }

    // ---- cross-warp m-half reduction via SMEM (reuses staging space) ----
    __syncthreads();
    float* red = (float*)sh;
    const int wslot = nw * 2 + mh;
    const uint32_t wbase = (uint32_t)(wslot * 32 + lid) * 33;
    // store the c-half this warp does NOT output (hh = 1-mh)
    #pragma unroll
    for (int nf = 0; nf < 2; nf++)
        #pragma unroll
        for (int j = 0; j < 4; j++)
            #pragma unroll
            for (int k = 0; k < 4; k++)
                red[wbase + nf * 16 + j * 4 + k] = acc[nf][(1 - mh) * 4 + j][k];
    __syncthreads();

    const int rslot = nw * 2 + (1 - mh);
    const uint32_t rbase = (uint32_t)(rslot * 32 + lid) * 33;

    // vsum for this warp's output c-half
    float vs0[4], vs1[4];
    #pragma unroll
    for (int j = 0; j < 4; j++) {
        int c = mh * 32 + j * 8 + 2 * t;
        vs0[j] = g_vsum[b * CC + c];
        vs1[j] = g_vsum[b * CC + c + 1];
    }

    #pragma unroll
    for (int nf = 0; nf < 2; nf++) {
        int n = n0 + nw * 32 + nf * 16 + g;
        #pragma unroll
        for (int j = 0; j < 4; j++) {
            int c = mh * 32 + j * 8 + 2 * t;
            float a0 = acc[nf][mh * 4 + j][0] + red[rbase + nf * 16 + j * 4 + 0];
            float a1 = acc[nf][mh * 4 + j][1] + red[rbase + nf * 16 + j * 4 + 1];
            float a2 = acc[nf][mh * 4 + j][2] + red[rbase + nf * 16 + j * 4 + 2];
            float a3 = acc[nf][mh * 4 + j][3] + red[rbase + nf * 16 + j * 4 + 3];
            size_t i00 = ((size_t)b * CC + c) * NN + n;
            size_t i01 = i00 + NN;
            out[i00]     = fmaf(0.5f, a0, vs0[j]) + x[i00];
            out[i01]     = fmaf(0.5f, a1, vs1[j]) + x[i01];
            out[i00 + 8] = fmaf(0.5f, a2, vs0[j]) + x[i00 + 8];
            out[i01 + 8] = fmaf(0.5f, a3, vs1[j]) + x[i01 + 8];
        }
    }
}

// ---------------- kernel 3: per-(b,c) mean & max over N ----------------
__global__ __launch_bounds__(256) void reduce_kernel(const float* __restrict__ out)
{
    __shared__ float ss[256], sm[256];
    int c = blockIdx.x, b = blockIdx.y;
    const float* row = out + ((size_t)b * CC + c) * NN;
    float s = 0.f, m = -3.4e38f;
    for (int i = threadIdx.x; i < NN / 4; i += 256) {
        float4 v = ((const float4*)row)[i];
        s += (v.x + v.y) + (v.z + v.w);
        m = fmaxf(m, fmaxf(fmaxf(v.x, v.y), fmaxf(v.z, v.w)));
    }
    ss[threadIdx.x] = s; sm[threadIdx.x] = m;
    __syncthreads();
    for (int o = 128; o > 0; o >>= 1) {
        if (threadIdx.x < o) {
            ss[threadIdx.x] += ss[threadIdx.x + o];
            sm[threadIdx.x] = fmaxf(sm[threadIdx.x], sm[threadIdx.x + o]);
        }
        __syncthreads();
    }
    if (threadIdx.x == 0) {
        g_avg[b * CC + c] = ss[0] * (1.0f / NN);
        g_mx[b * CC + c]  = sm[0];
    }
}

// ---------------- kernel 4: CBAM scale (inline) + apply ----------------
__global__ __launch_bounds__(256) void apply_scale_kernel(
    float* __restrict__ out,
    const float* __restrict__ w1, const float* __restrict__ w2)
{
    __shared__ float sc;
    int bc = blockIdx.x;
    int b = bc >> 6, c = bc & 63;
    if (threadIdx.x == 0) {
        float y = 0.f;
        #pragma unroll
        for (int r = 0; r < 4; r++) {
            float ha = 0.f, hm = 0.f;
            #pragma unroll 16
            for (int cc = 0; cc < 64; cc++) {
                float w = w1[r * 64 + cc];
                ha += w * g_avg[b * 64 + cc];
                hm += w * g_mx[b * 64 + cc];
            }
            float wv = w2[c * 4 + r];
            y += wv * fmaxf(ha, 0.f) + wv * fmaxf(hm, 0.f);
        }
        sc = 1.0f / (1.0f + expf(-y));
    }
    __syncthreads();
    float s = sc;
    float4* row = (float4*)(out + (size_t)bc * NN);
    for (int i = threadIdx.x; i < NN / 4; i += 256) {
        float4 v = row[i];
        v.x *= s; v.y *= s; v.z *= s; v.w *= s;
        row[i] = v;
    }
}

// ---------------- launch ----------------
extern "C" void kernel_launch(void* const* d_in, const int* in_sizes, int n_in,
                              void* d_out, int out_size)
{
    const float* x     = (const float*)d_in[0];
    const float* wq    = (const float*)d_in[1];
    const float* bq    = (const float*)d_in[2];
    const float* wk    = (const float*)d_in[3];
    const float* bk    = (const float*)d_in[4];
    const float* wv    = (const float*)d_in[5];
    const float* bv    = (const float*)d_in[6];
    const float* ca_w1 = (const float*)d_in[7];
    const float* ca_w2 = (const float*)d_in[8];
    float* out = (float*)d_out;

    cudaFuncSetAttribute(attn_mma_kernel, cudaFuncAttributeMaxDynamicSharedMemorySize, SMEM_BYTES);

    qkv_kernel<<<dim3(NN / 256, BB), 256>>>(x, wq, bq, wk, bk, wv, bv);
    vsum_kernel<<<BB * CC, 256>>>();
    attn_mma_kernel<<<dim3(NN / TN, BB), 512, SMEM_BYTES>>>(x, out);
    reduce_kernel<<<dim3(CC, BB), 256>>>(out);
    apply_scale_kernel<<<BB * CC, 256>>>(out, ca_w1, ca_w2);
}

// round 7
// speedup vs baseline: 1.0762x; 1.0762x over previous
#include <cuda_runtime.h>
#include <cuda_fp16.h>
#include <cstdint>

#define BB 4
#define CC 64
#define C8 8
#define NN 9216          // 96*96
#define TN 128           // queries per CTA
#define TM 64            // key/value chunk
#define NCHUNK (NN/TM)   // 144
#define KST 72           // Ks row stride (floats)
#define VST 80           // Vs row stride (halfs)

typedef unsigned long long u64;

// ---------------- scratch ----------------
__device__ float    g_Qn[(size_t)BB * NN * C8];          // [b][n][k] tf32, pre-halved
__device__ float    g_Kp[(size_t)BB * NCHUNK * C8 * TM]; // [b][ch][k][m] tf32
__device__ __half   g_Vp[(size_t)BB * NCHUNK * CC * TM]; // [b][ch][c][m'] f16, m-perm
__device__ float    g_vsum[BB * CC];                     // 0.5 * sum_m V_f16
__device__ float    g_sum[BB * CC];                      // sum over n of out (atomic)
__device__ uint32_t g_mxk[BB * CC];                      // max over n of out (key-coded)

__device__ __forceinline__ float to_tf32(float v) {
    asm("cvt.rna.tf32.f32 %0, %0;" : "+f"(v));
    return v;
}
__device__ __forceinline__ float th(float x) {      // MUFU.TANH
    asm("tanh.approx.f32 %0, %0;" : "+f"(x));
    return x;
}
__device__ __forceinline__ uint32_t pk(float lo, float hi) {  // f16x2 {lo,hi}
    uint32_t r;
    asm("cvt.rn.f16x2.f32 %0, %1, %2;" : "=r"(r) : "f"(hi), "f"(lo));
    return r;
}
__device__ __forceinline__ uint32_t fb(float v) { return __float_as_uint(v); }
__device__ __forceinline__ uint32_t smem_u32(const void* p) {
    uint32_t a;
    asm("{ .reg .u64 t; cvta.to.shared.u64 t, %1; cvt.u32.u64 %0, t; }" : "=r"(a) : "l"(p));
    return a;
}
// order-preserving float->uint key for atomicMax
__device__ __forceinline__ uint32_t fkey(float f) {
    uint32_t u = __float_as_uint(f);
    return (u >> 31) ? ~u : (u | 0x80000000u);
}
__device__ __forceinline__ float fdec(uint32_t k) {
    return (k >> 31) ? __uint_as_float(k & 0x7FFFFFFFu) : __uint_as_float(~k);
}
// f32x2 helpers
__device__ __forceinline__ u64 f2_fma(u64 a, u64 b, u64 c) {
    u64 d;
    asm("fma.rn.f32x2 %0, %1, %2, %3;" : "=l"(d) : "l"(a), "l"(b), "l"(c));
    return d;
}
__device__ __forceinline__ u64 f2_pack(float lo, float hi) {
    u64 d; asm("mov.b64 %0, {%1, %2};" : "=l"(d) : "f"(lo), "f"(hi)); return d;
}
__device__ __forceinline__ void f2_unpack(u64 v, float &lo, float &hi) {
    asm("mov.b64 {%0, %1}, %2;" : "=f"(lo), "=f"(hi) : "l"(v));
}

__device__ __forceinline__ void mma8(float d[4], const uint32_t a[4], uint32_t b0, uint32_t b1) {
    asm volatile(
        "mma.sync.aligned.m16n8k8.row.col.f32.tf32.tf32.f32 "
        "{%0,%1,%2,%3}, {%4,%5,%6,%7}, {%8,%9}, {%0,%1,%2,%3};"
        : "+f"(d[0]), "+f"(d[1]), "+f"(d[2]), "+f"(d[3])
        : "r"(a[0]), "r"(a[1]), "r"(a[2]), "r"(a[3]), "r"(b0), "r"(b1));
}
__device__ __forceinline__ void mma16(float d[4], const uint32_t a[4], uint32_t b0, uint32_t b1) {
    asm volatile(
        "mma.sync.aligned.m16n8k16.row.col.f32.f16.f16.f32 "
        "{%0,%1,%2,%3}, {%4,%5,%6,%7}, {%8,%9}, {%0,%1,%2,%3};"
        : "+f"(d[0]), "+f"(d[1]), "+f"(d[2]), "+f"(d[3])
        : "r"(a[0]), "r"(a[1]), "r"(a[2]), "r"(a[3]), "r"(b0), "r"(b1));
}

#define CP16(dst, src) \
    asm volatile("cp.async.cg.shared.global [%0], [%1], 16;" :: "r"(dst), "l"(src))
#define CP_COMMIT() asm volatile("cp.async.commit_group;" ::: "memory")
#define CP_WAIT0()  asm volatile("cp.async.wait_group 0;" ::: "memory")

// ---------------- kernel 0: init atomic accumulators ----------------
__global__ void init_kernel()
{
    int t = threadIdx.x;
    g_sum[t] = 0.0f;
    g_mxk[t] = 0u;
}

// ---------------- kernel 1: fused 1x1-conv Q/K/V (f32x2, Q pre-halved) --------
__global__ __launch_bounds__(256) void qkv_kernel(
    const float* __restrict__ x,
    const float* __restrict__ wq, const float* __restrict__ bq,
    const float* __restrict__ wk, const float* __restrict__ bk,
    const float* __restrict__ wv, const float* __restrict__ bv)
{
    __shared__ float sw[80 * 64];
    __shared__ float sb[80];
    int tid = threadIdx.x;
    for (int i = tid; i < 512;  i += 256) sw[i] = wq[i];
    for (int i = tid; i < 512;  i += 256) sw[512 + i] = wk[i];
    for (int i = tid; i < 4096; i += 256) sw[1024 + i] = wv[i];
    if (tid < 80) sb[tid] = (tid < 8) ? bq[tid] : (tid < 16 ? bk[tid - 8] : bv[tid - 16]);
    __syncthreads();

    int n = blockIdx.x * 256 + tid;
    int b = blockIdx.y;
    const float* xb = x + (size_t)b * CC * NN + n;
    u64 xp[32];
    #pragma unroll
    for (int c = 0; c < 32; c++)
        xp[c] = f2_pack(xb[(size_t)(2 * c) * NN], xb[(size_t)(2 * c + 1) * NN]);

    const int ch = n >> 6;
    const int m  = n & 63;
    const int P = (m & 15) >> 1;
    const int mphys = (m & ~15) | ((((P & 3) * 2 + (P >> 2)) << 1) | (m & 1));

    float* qrow  = g_Qn + ((size_t)b * NN + n) * C8;
    float* ktile = g_Kp + ((size_t)(b * NCHUNK + ch) * C8) * TM;
    #pragma unroll 1
    for (int o = 0; o < C8; o++) {
        const u64* wqr = (const u64*)(sw + o * 64);
        const u64* wkr = (const u64*)(sw + 512 + o * 64);
        u64 aq2 = 0ULL, ak2 = 0ULL;
        #pragma unroll
        for (int c = 0; c < 32; c++) {
            aq2 = f2_fma(wqr[c], xp[c], aq2);
            ak2 = f2_fma(wkr[c], xp[c], ak2);
        }
        float ql, qh, kl, kh;
        f2_unpack(aq2, ql, qh); f2_unpack(ak2, kl, kh);
        qrow[o] = to_tf32(0.5f * (sb[o] + ql + qh));        // fold tanh's /2 into Q
        ktile[o * TM + m] = to_tf32(sb[8 + o] + kl + kh);
    }
    __half* vtile = g_Vp + ((size_t)(b * NCHUNK + ch) * CC) * TM;
    #pragma unroll 1
    for (int o = 0; o < CC; o++) {
        const u64* wvr = (const u64*)(sw + 1024 + o * 64);
        u64 av2 = 0ULL;
        #pragma unroll
        for (int c = 0; c < 32; c++) av2 = f2_fma(wvr[c], xp[c], av2);
        float vl, vh;
        f2_unpack(av2, vl, vh);
        vtile[o * TM + mphys] = __float2half_rn(sb[16 + o] + vl + vh);
    }
}

// ---------------- kernel 1b: vsum[b][c] = 0.5 * sum_m V_f16 ----------------
__global__ __launch_bounds__(256) void vsum_kernel()
{
    __shared__ float ss[256];
    int bc = blockIdx.x;
    int b = bc >> 6, c = bc & 63;
    const __half* vb = g_Vp + (size_t)b * NCHUNK * CC * TM + (size_t)c * TM;
    float s = 0.f;
    for (int i = threadIdx.x; i < NCHUNK * TM; i += 256) {
        int ch = i >> 6, m = i & 63;
        s += __half2float(vb[(size_t)ch * CC * TM + m]);
    }
    ss[threadIdx.x] = s;
    __syncthreads();
    for (int o = 128; o > 0; o >>= 1) {
        if (threadIdx.x < o) ss[threadIdx.x] += ss[threadIdx.x + o];
        __syncthreads();
    }
    if (threadIdx.x == 0) g_vsum[bc] = 0.5f * ss[0];
}

// ---------------- kernel 2: fused tanh-attention + reduction epilogue --------
// 8 warps; warp w owns n rows [w*16, w*16+16), all 64 m per chunk. (R4 shape)
__global__ __launch_bounds__(256, 2) void attn_mma_kernel(
    const float* __restrict__ x, float* __restrict__ out)
{
    __shared__ float  Ks[2][C8 * KST];
    __shared__ __half Vs[2][CC * VST];

    const int tid = threadIdx.x, wid = tid >> 5, lid = tid & 31;
    const int g = lid >> 2, t = lid & 3;
    const int b = blockIdx.y, n0 = blockIdx.x * TN;

    const uint32_t ksb = smem_u32(&Ks[0][0]);
    const uint32_t vsb = smem_u32(&Vs[0][0]);

    uint32_t qa[4];
    {
        const float* q0 = g_Qn + ((size_t)b * NN + n0 + wid * 16 + g) * C8;
        qa[0] = fb(q0[t]);
        qa[1] = fb(q0[8 * C8 + t]);
        qa[2] = fb(q0[t + 4]);
        qa[3] = fb(q0[8 * C8 + t + 4]);
    }

    float acc[8][4];
    #pragma unroll
    for (int j = 0; j < 8; j++)
        #pragma unroll
        for (int k = 0; k < 4; k++) acc[j][k] = 0.0f;

    const float*  kbase = g_Kp + (size_t)b * NCHUNK * C8 * TM;
    const __half* vbase = g_Vp + (size_t)b * NCHUNK * CC * TM;

    auto stage = [&](int ch, int p) {
        if (tid < 128) {
            int k = tid >> 4, seg = tid & 15;
            CP16(ksb + (uint32_t)(p * C8 * KST * 4 + k * (KST * 4) + seg * 16),
                 (const char*)(kbase + (size_t)ch * C8 * TM + k * TM) + seg * 16);
        }
        #pragma unroll
        for (int r = 0; r < 2; r++) {
            int pc = tid + r * 256;
            int c = pc >> 3, seg = pc & 7;
            CP16(vsb + (uint32_t)(p * CC * VST * 2 + c * (VST * 2) + seg * 16),
                 (const char*)(vbase + (size_t)ch * CC * TM + c * TM) + seg * 16);
        }
    };

    stage(0, 0);
    CP_COMMIT();

    for (int ch = 0; ch < NCHUNK; ch++) {
        const int p = ch & 1;
        CP_WAIT0();
        __syncthreads();
        if (ch + 1 < NCHUNK) { stage(ch + 1, p ^ 1); CP_COMMIT(); }

        // GEMM1: e[mt] = (Q/2).K^T over 8 m-tiles of 8
        float e[8][4];
        #pragma unroll
        for (int mt = 0; mt < 8; mt++) {
            e[mt][0] = e[mt][1] = e[mt][2] = e[mt][3] = 0.0f;
            uint32_t b0 = fb(Ks[p][t * KST + mt * 8 + g]);
            uint32_t b1 = fb(Ks[p][(t + 4) * KST + mt * 8 + g]);
            mma8(e[mt], qa, b0, b1);
        }

        // tanh -> f16x2 A-fragments (registers)
        uint32_t af[4][4];
        #pragma unroll
        for (int ks = 0; ks < 4; ks++) {
            af[ks][0] = pk(th(e[2 * ks][0]),     th(e[2 * ks][1]));
            af[ks][1] = pk(th(e[2 * ks][2]),     th(e[2 * ks][3]));
            af[ks][2] = pk(th(e[2 * ks + 1][0]), th(e[2 * ks + 1][1]));
            af[ks][3] = pk(th(e[2 * ks + 1][2]), th(e[2 * ks + 1][3]));
        }

        // GEMM2: acc[n16 x c64] += tanh * V
        #pragma unroll
        for (int ks = 0; ks < 4; ks++) {
            #pragma unroll
            for (int j = 0; j < 8; j++) {
                uint2 bv = *(const uint2*)(&Vs[p][(8 * j + g) * VST + ks * 16 + 4 * t]);
                mma16(acc[j], af[ks], bv.x, bv.y);
            }
        }
    }

    // ---- epilogue: out = vsum + 0.5*acc + x; fused mean/max reduction ----
    const int n = n0 + wid * 16 + g;
    #pragma unroll
    for (int j = 0; j < 8; j++) {
        int c = 8 * j + 2 * t;
        float vs0 = g_vsum[b * CC + c];
        float vs1 = g_vsum[b * CC + c + 1];
        size_t i00 = ((size_t)b * CC + c) * NN + n;
        size_t i01 = i00 + NN;
        float f0 = fmaf(0.5f, acc[j][0], vs0) + x[i00];
        float f1 = fmaf(0.5f, acc[j][1], vs1) + x[i01];
        float f2v = fmaf(0.5f, acc[j][2], vs0) + x[i00 + 8];
        float f3 = fmaf(0.5f, acc[j][3], vs1) + x[i01 + 8];
        out[i00]     = f0;
        out[i01]     = f1;
        out[i00 + 8] = f2v;
        out[i01 + 8] = f3;

        // reduce over this warp's 16 n-rows (g lanes, stride 4)
        float sc  = f0 + f2v,            sc1 = f1 + f3;
        float mc  = fmaxf(f0, f2v),      mc1 = fmaxf(f1, f3);
        #pragma unroll
        for (int off = 16; off >= 4; off >>= 1) {
            sc  += __shfl_down_sync(0xFFFFFFFFu, sc,  off);
            sc1 += __shfl_down_sync(0xFFFFFFFFu, sc1, off);
            mc   = fmaxf(mc,  __shfl_down_sync(0xFFFFFFFFu, mc,  off));
            mc1  = fmaxf(mc1, __shfl_down_sync(0xFFFFFFFFu, mc1, off));
        }
        if (lid < 4) {
            atomicAdd(&g_sum[b * CC + c],     sc);
            atomicAdd(&g_sum[b * CC + c + 1], sc1);
            atomicMax(&g_mxk[b * CC + c],     fkey(mc));
            atomicMax(&g_mxk[b * CC + c + 1], fkey(mc1));
        }
    }
}

// ---------------- kernel 3: CBAM MLP (from fused reductions) + apply ----------
__global__ __launch_bounds__(256) void apply_scale_kernel(
    float* __restrict__ out,
    const float* __restrict__ w1, const float* __restrict__ w2)
{
    __shared__ float red[512];
    __shared__ float scale_s;
    const int bc = blockIdx.x;
    const int b = bc >> 6, c = bc & 63;
    const int tid = threadIdx.x;
    const int r = tid >> 6, cc = tid & 63;

    float av = g_sum[b * CC + cc] * (1.0f / NN);
    float mx = fdec(g_mxk[b * CC + cc]);
    float w  = w1[r * 64 + cc];
    red[tid]       = w * av;
    red[256 + tid] = w * mx;
    __syncthreads();
    #pragma unroll
    for (int o = 32; o > 0; o >>= 1) {
        if (cc < o) {
            red[tid]       += red[tid + o];
            red[256 + tid] += red[256 + tid + o];
        }
        __syncthreads();
    }
    if (tid == 0) {
        float y = 0.f;
        #pragma unroll
        for (int rr = 0; rr < 4; rr++)
            y += w2[c * 4 + rr] * (fmaxf(red[rr * 64], 0.f) + fmaxf(red[256 + rr * 64], 0.f));
        scale_s = 1.0f / (1.0f + expf(-y));
    }
    __syncthreads();
    const float s = scale_s;
    float4* row = (float4*)(out + (size_t)bc * NN);
    for (int i = tid; i < NN / 4; i += 256) {
        float4 v = row[i];
        v.x *= s; v.y *= s; v.z *= s; v.w *= s;
        row[i] = v;
    }
}

// ---------------- launch ----------------
extern "C" void kernel_launch(void* const* d_in, const int* in_sizes, int n_in,
                              void* d_out, int out_size)
{
    const float* x     = (const float*)d_in[0];
    const float* wq    = (const float*)d_in[1];
    const float* bq    = (const float*)d_in[2];
    const float* wk    = (const float*)d_in[3];
    const float* bk    = (const float*)d_in[4];
    const float* wv    = (const float*)d_in[5];
    const float* bv    = (const float*)d_in[6];
    const float* ca_w1 = (const float*)d_in[7];
    const float* ca_w2 = (const float*)d_in[8];
    float* out = (float*)d_out;

    init_kernel<<<1, 256>>>();
    qkv_kernel<<<dim3(NN / 256, BB), 256>>>(x, wq, bq, wk, bk, wv, bv);
    vsum_kernel<<<BB * CC, 256>>>();
    attn_mma_kernel<<<dim3(NN / TN, BB), 256>>>(x, out);
    apply_scale_kernel<<<BB * CC, 256>>>(out, ca_w1, ca_w2);
}

// round 8
// speedup vs baseline: 1.1001x; 1.0222x over previous
#include <cuda_runtime.h>
#include <cuda_fp16.h>
#include <cstdint>

#define BB 4
#define CC 64
#define C8 8
#define NN 9216          // 96*96
#define TN 128           // queries per CTA
#define TM 64            // key/value chunk
#define NCHUNK (NN/TM)   // 144
#define KST 72           // Ks row stride (floats)
#define VST 80           // Vs row stride (halfs)

typedef unsigned long long u64;

// ---------------- scratch ----------------
__device__ float    g_Qn[(size_t)BB * NN * C8];          // [b][n][k] tf32, pre-halved
__device__ float    g_Kp[(size_t)BB * NCHUNK * C8 * TM]; // [b][ch][k][m] tf32
__device__ __half   g_Vp[(size_t)BB * NCHUNK * CC * TM]; // [b][ch][c][m'] f16, m-perm
__device__ float    g_vsum[BB * CC];                     // 0.5 * sum_m V_f16
__device__ float    g_sum[BB * CC];                      // sum over n of out (atomic)
__device__ uint32_t g_mxk[BB * CC];                      // max over n of out (key-coded)

__device__ __forceinline__ float to_tf32(float v) {
    asm("cvt.rna.tf32.f32 %0, %0;" : "+f"(v));
    return v;
}
__device__ __forceinline__ float th(float x) {      // MUFU.TANH
    asm("tanh.approx.f32 %0, %0;" : "+f"(x));
    return x;
}
__device__ __forceinline__ uint32_t pk(float lo, float hi) {  // f16x2 {lo,hi}
    uint32_t r;
    asm("cvt.rn.f16x2.f32 %0, %1, %2;" : "=r"(r) : "f"(hi), "f"(lo));
    return r;
}
__device__ __forceinline__ uint32_t fb(float v) { return __float_as_uint(v); }
__device__ __forceinline__ uint32_t smem_u32(const void* p) {
    uint32_t a;
    asm("{ .reg .u64 t; cvta.to.shared.u64 t, %1; cvt.u32.u64 %0, t; }" : "=r"(a) : "l"(p));
    return a;
}
__device__ __forceinline__ uint32_t fkey(float f) {
    uint32_t u = __float_as_uint(f);
    return (u >> 31) ? ~u : (u | 0x80000000u);
}
__device__ __forceinline__ float fdec(uint32_t k) {
    return (k >> 31) ? __uint_as_float(k & 0x7FFFFFFFu) : __uint_as_float(~k);
}
__device__ __forceinline__ u64 f2_fma(u64 a, u64 b, u64 c) {
    u64 d;
    asm("fma.rn.f32x2 %0, %1, %2, %3;" : "=l"(d) : "l"(a), "l"(b), "l"(c));
    return d;
}
__device__ __forceinline__ u64 f2_pack(float lo, float hi) {
    u64 d; asm("mov.b64 %0, {%1, %2};" : "=l"(d) : "f"(lo), "f"(hi)); return d;
}
__device__ __forceinline__ void f2_unpack(u64 v, float &lo, float &hi) {
    asm("mov.b64 {%0, %1}, %2;" : "=f"(lo), "=f"(hi) : "l"(v));
}

__device__ __forceinline__ void mma8(float d[4], const uint32_t a[4], uint32_t b0, uint32_t b1) {
    asm volatile(
        "mma.sync.aligned.m16n8k8.row.col.f32.tf32.tf32.f32 "
        "{%0,%1,%2,%3}, {%4,%5,%6,%7}, {%8,%9}, {%0,%1,%2,%3};"
        : "+f"(d[0]), "+f"(d[1]), "+f"(d[2]), "+f"(d[3])
        : "r"(a[0]), "r"(a[1]), "r"(a[2]), "r"(a[3]), "r"(b0), "r"(b1));
}
__device__ __forceinline__ void mma16(float d[4], const uint32_t a[4], uint32_t b0, uint32_t b1) {
    asm volatile(
        "mma.sync.aligned.m16n8k16.row.col.f32.f16.f16.f32 "
        "{%0,%1,%2,%3}, {%4,%5,%6,%7}, {%8,%9}, {%0,%1,%2,%3};"
        : "+f"(d[0]), "+f"(d[1]), "+f"(d[2]), "+f"(d[3])
        : "r"(a[0]), "r"(a[1]), "r"(a[2]), "r"(a[3]), "r"(b0), "r"(b1));
}

#define CP16(dst, src) \
    asm volatile("cp.async.cg.shared.global [%0], [%1], 16;" :: "r"(dst), "l"(src))
#define CP_COMMIT() asm volatile("cp.async.commit_group;" ::: "memory")
#define CP_WAIT0()  asm volatile("cp.async.wait_group 0;" ::: "memory")

// dynamic SMEM: staging [0,25088) ; reduction reuses [0,33792)
#define SOFF_V 4608
#define SMEM_BYTES 33792

// ---------------- kernel 0: init atomic accumulators ----------------
__global__ void init_kernel()
{
    int t = threadIdx.x;
    g_sum[t] = 0.0f;
    g_mxk[t] = 0u;
}

// ---------------- kernel 1: fused 1x1-conv Q/K/V (f32x2, Q pre-halved) --------
__global__ __launch_bounds__(256) void qkv_kernel(
    const float* __restrict__ x,
    const float* __restrict__ wq, const float* __restrict__ bq,
    const float* __restrict__ wk, const float* __restrict__ bk,
    const float* __restrict__ wv, const float* __restrict__ bv)
{
    __shared__ float sw[80 * 64];
    __shared__ float sb[80];
    int tid = threadIdx.x;
    for (int i = tid; i < 512;  i += 256) sw[i] = wq[i];
    for (int i = tid; i < 512;  i += 256) sw[512 + i] = wk[i];
    for (int i = tid; i < 4096; i += 256) sw[1024 + i] = wv[i];
    if (tid < 80) sb[tid] = (tid < 8) ? bq[tid] : (tid < 16 ? bk[tid - 8] : bv[tid - 16]);
    __syncthreads();

    int n = blockIdx.x * 256 + tid;
    int b = blockIdx.y;
    const float* xb = x + (size_t)b * CC * NN + n;
    u64 xp[32];
    #pragma unroll
    for (int c = 0; c < 32; c++)
        xp[c] = f2_pack(xb[(size_t)(2 * c) * NN], xb[(size_t)(2 * c + 1) * NN]);

    const int ch = n >> 6;
    const int m  = n & 63;
    const int P = (m & 15) >> 1;
    const int mphys = (m & ~15) | ((((P & 3) * 2 + (P >> 2)) << 1) | (m & 1));

    float* qrow  = g_Qn + ((size_t)b * NN + n) * C8;
    float* ktile = g_Kp + ((size_t)(b * NCHUNK + ch) * C8) * TM;
    #pragma unroll 1
    for (int o = 0; o < C8; o++) {
        const u64* wqr = (const u64*)(sw + o * 64);
        const u64* wkr = (const u64*)(sw + 512 + o * 64);
        u64 aq2 = 0ULL, ak2 = 0ULL;
        #pragma unroll
        for (int c = 0; c < 32; c++) {
            aq2 = f2_fma(wqr[c], xp[c], aq2);
            ak2 = f2_fma(wkr[c], xp[c], ak2);
        }
        float ql, qh, kl, kh;
        f2_unpack(aq2, ql, qh); f2_unpack(ak2, kl, kh);
        qrow[o] = to_tf32(0.5f * (sb[o] + ql + qh));        // fold tanh's /2 into Q
        ktile[o * TM + m] = to_tf32(sb[8 + o] + kl + kh);
    }
    __half* vtile = g_Vp + ((size_t)(b * NCHUNK + ch) * CC) * TM;
    #pragma unroll 1
    for (int o = 0; o < CC; o++) {
        const u64* wvr = (const u64*)(sw + 1024 + o * 64);
        u64 av2 = 0ULL;
        #pragma unroll
        for (int c = 0; c < 32; c++) av2 = f2_fma(wvr[c], xp[c], av2);
        float vl, vh;
        f2_unpack(av2, vl, vh);
        vtile[o * TM + mphys] = __float2half_rn(sb[16 + o] + vl + vh);
    }
}

// ---------------- kernel 1b: vsum[b][c] = 0.5 * sum_m V_f16 ----------------
__global__ __launch_bounds__(256) void vsum_kernel()
{
    __shared__ float ss[256];
    int bc = blockIdx.x;
    int b = bc >> 6, c = bc & 63;
    const __half* vb = g_Vp + (size_t)b * NCHUNK * CC * TM + (size_t)c * TM;
    float s = 0.f;
    for (int i = threadIdx.x; i < NCHUNK * TM; i += 256) {
        int ch = i >> 6, m = i & 63;
        s += __half2float(vb[(size_t)ch * CC * TM + m]);
    }
    ss[threadIdx.x] = s;
    __syncthreads();
    for (int o = 128; o > 0; o >>= 1) {
        if (threadIdx.x < o) ss[threadIdx.x] += ss[threadIdx.x + o];
        __syncthreads();
    }
    if (threadIdx.x == 0) g_vsum[bc] = 0.5f * ss[0];
}

// ---------------- kernel 2: fused tanh-attention, m-split, fused reductions ---
// 8 warps: nw = wid&3 -> 32 query rows (2 A-frags); mh = wid>>2 -> m-half of 32.
// Each B-fragment LDS feeds 2 MMAs -> V crossbar traffic halves vs R7.
__global__ __launch_bounds__(256, 2) void attn_mma_kernel(
    const float* __restrict__ x, float* __restrict__ out)
{
    extern __shared__ char sh[];
    float  (*Ks)[C8 * KST] = (float (*)[C8 * KST])(sh);
    __half (*Vs)[CC * VST] = (__half (*)[CC * VST])(sh + SOFF_V);
    const uint32_t ksb = smem_u32(sh);
    const uint32_t vsb = ksb + SOFF_V;

    const int tid = threadIdx.x, wid = tid >> 5, lid = tid & 31;
    const int g = lid >> 2, t = lid & 3;
    const int b = blockIdx.y, n0 = blockIdx.x * TN;
    const int nw = wid & 3, mh = wid >> 2;

    // Q A-fragments (persistent), 2 n-frags of 16 rows
    uint32_t qa[2][4];
    #pragma unroll
    for (int nf = 0; nf < 2; nf++) {
        const float* q0 = g_Qn + ((size_t)b * NN + n0 + nw * 32 + nf * 16 + g) * C8;
        qa[nf][0] = fb(q0[t]);
        qa[nf][1] = fb(q0[8 * C8 + t]);
        qa[nf][2] = fb(q0[t + 4]);
        qa[nf][3] = fb(q0[8 * C8 + t + 4]);
    }

    float acc[2][8][4];
    #pragma unroll
    for (int nf = 0; nf < 2; nf++)
        #pragma unroll
        for (int j = 0; j < 8; j++)
            #pragma unroll
            for (int k = 0; k < 4; k++) acc[nf][j][k] = 0.0f;

    const float*  kbase = g_Kp + (size_t)b * NCHUNK * C8 * TM;
    const __half* vbase = g_Vp + (size_t)b * NCHUNK * CC * TM;

    auto stage = [&](int ch, int p) {
        if (tid < 128) {
            int k = tid >> 4, seg = tid & 15;
            CP16(ksb + (uint32_t)(p * C8 * KST * 4 + k * (KST * 4) + seg * 16),
                 (const char*)(kbase + (size_t)ch * C8 * TM + k * TM) + seg * 16);
        }
        #pragma unroll
        for (int r = 0; r < 2; r++) {
            int pc = tid + r * 256;
            int c = pc >> 3, seg = pc & 7;
            CP16(vsb + (uint32_t)(p * CC * VST * 2 + c * (VST * 2) + seg * 16),
                 (const char*)(vbase + (size_t)ch * CC * TM + c * TM) + seg * 16);
        }
    };

    stage(0, 0);
    CP_COMMIT();

    for (int ch = 0; ch < NCHUNK; ch++) {
        const int p = ch & 1;
        CP_WAIT0();
        __syncthreads();
        if (ch + 1 < NCHUNK) { stage(ch + 1, p ^ 1); CP_COMMIT(); }

        // K B-fragments for this warp's m-half (shared across both n-frags)
        uint32_t kb0[4], kb1[4];
        #pragma unroll
        for (int mt = 0; mt < 4; mt++) {
            kb0[mt] = fb(Ks[p][t * KST + mh * 32 + mt * 8 + g]);
            kb1[mt] = fb(Ks[p][(t + 4) * KST + mh * 32 + mt * 8 + g]);
        }

        // GEMM1 + tanh -> f16x2 A-fragments (per nf to bound live regs)
        uint32_t af[2][2][4];
        #pragma unroll
        for (int nf = 0; nf < 2; nf++) {
            float e[4][4];
            #pragma unroll
            for (int mt = 0; mt < 4; mt++) {
                e[mt][0] = e[mt][1] = e[mt][2] = e[mt][3] = 0.0f;
                mma8(e[mt], qa[nf], kb0[mt], kb1[mt]);
            }
            #pragma unroll
            for (int ks = 0; ks < 2; ks++) {
                af[nf][ks][0] = pk(th(e[2 * ks][0]),     th(e[2 * ks][1]));
                af[nf][ks][1] = pk(th(e[2 * ks][2]),     th(e[2 * ks][3]));
                af[nf][ks][2] = pk(th(e[2 * ks + 1][0]), th(e[2 * ks + 1][1]));
                af[nf][ks][3] = pk(th(e[2 * ks + 1][2]), th(e[2 * ks + 1][3]));
            }
        }

        // GEMM2: each B-fragment load feeds both n-frags
        #pragma unroll
        for (int ks = 0; ks < 2; ks++) {
            #pragma unroll
            for (int j = 0; j < 8; j++) {
                uint2 bv = *(const uint2*)(&Vs[p][(8 * j + g) * VST + mh * 32 + ks * 16 + 4 * t]);
                mma16(acc[0][j], af[0][ks], bv.x, bv.y);
                mma16(acc[1][j], af[1][ks], bv.x, bv.y);
            }
        }
    }

    // ---- cross-warp m-half reduction via SMEM (reuses staging space) ----
    __syncthreads();
    float* red = (float*)sh;
    const int wslot = nw * 2 + mh;
    const uint32_t wbase = (uint32_t)(wslot * 32 + lid) * 33;
    #pragma unroll
    for (int nf = 0; nf < 2; nf++)
        #pragma unroll
        for (int j = 0; j < 4; j++)
            #pragma unroll
            for (int k = 0; k < 4; k++)
                red[wbase + nf * 16 + j * 4 + k] = acc[nf][(1 - mh) * 4 + j][k];
    __syncthreads();

    const int rslot = nw * 2 + (1 - mh);
    const uint32_t rbase = (uint32_t)(rslot * 32 + lid) * 33;

    // ---- epilogue: out = vsum + 0.5*acc + x; fused mean/max reduction ----
    #pragma unroll
    for (int j = 0; j < 4; j++) {
        const int c = mh * 32 + j * 8 + 2 * t;
        const float vs0 = g_vsum[b * CC + c];
        const float vs1 = g_vsum[b * CC + c + 1];
        float sc = 0.f, sc1 = 0.f, mc = -3.4e38f, mc1 = -3.4e38f;
        #pragma unroll
        for (int nf = 0; nf < 2; nf++) {
            const int n = n0 + nw * 32 + nf * 16 + g;
            float a0 = acc[nf][mh * 4 + j][0] + red[rbase + nf * 16 + j * 4 + 0];
            float a1 = acc[nf][mh * 4 + j][1] + red[rbase + nf * 16 + j * 4 + 1];
            float a2 = acc[nf][mh * 4 + j][2] + red[rbase + nf * 16 + j * 4 + 2];
            float a3 = acc[nf][mh * 4 + j][3] + red[rbase + nf * 16 + j * 4 + 3];
            size_t i00 = ((size_t)b * CC + c) * NN + n;
            size_t i01 = i00 + NN;
            float f0  = fmaf(0.5f, a0, vs0) + x[i00];
            float f1  = fmaf(0.5f, a1, vs1) + x[i01];
            float f2v = fmaf(0.5f, a2, vs0) + x[i00 + 8];
            float f3  = fmaf(0.5f, a3, vs1) + x[i01 + 8];
            out[i00]     = f0;
            out[i01]     = f1;
            out[i00 + 8] = f2v;
            out[i01 + 8] = f3;
            sc  += f0 + f2v;        sc1 += f1 + f3;
            mc   = fmaxf(mc,  fmaxf(f0, f2v));
            mc1  = fmaxf(mc1, fmaxf(f1, f3));
        }
        #pragma unroll
        for (int off = 16; off >= 4; off >>= 1) {
            sc  += __shfl_down_sync(0xFFFFFFFFu, sc,  off);
            sc1 += __shfl_down_sync(0xFFFFFFFFu, sc1, off);
            mc   = fmaxf(mc,  __shfl_down_sync(0xFFFFFFFFu, mc,  off));
            mc1  = fmaxf(mc1, __shfl_down_sync(0xFFFFFFFFu, mc1, off));
        }
        if (lid < 4) {
            atomicAdd(&g_sum[b * CC + c],     sc);
            atomicAdd(&g_sum[b * CC + c + 1], sc1);
            atomicMax(&g_mxk[b * CC + c],     fkey(mc));
            atomicMax(&g_mxk[b * CC + c + 1], fkey(mc1));
        }
    }
}

// ---------------- kernel 3: CBAM MLP (from fused reductions) + apply ----------
__global__ __launch_bounds__(256) void apply_scale_kernel(
    float* __restrict__ out,
    const float* __restrict__ w1, const float* __restrict__ w2)
{
    __shared__ float red[512];
    __shared__ float scale_s;
    const int bc = blockIdx.x;
    const int b = bc >> 6, c = bc & 63;
    const int tid = threadIdx.x;
    const int r = tid >> 6, cc = tid & 63;

    float av = g_sum[b * CC + cc] * (1.0f / NN);
    float mx = fdec(g_mxk[b * CC + cc]);
    float w  = w1[r * 64 + cc];
    red[tid]       = w * av;
    red[256 + tid] = w * mx;
    __syncthreads();
    #pragma unroll
    for (int o = 32; o > 0; o >>= 1) {
        if (cc < o) {
            red[tid]       += red[tid + o];
            red[256 + tid] += red[256 + tid + o];
        }
        __syncthreads();
    }
    if (tid == 0) {
        float y = 0.f;
        #pragma unroll
        for (int rr = 0; rr < 4; rr++)
            y += w2[c * 4 + rr] * (fmaxf(red[rr * 64], 0.f) + fmaxf(red[256 + rr * 64], 0.f));
        scale_s = 1.0f / (1.0f + expf(-y));
    }
    __syncthreads();
    const float s = scale_s;
    float4* row = (float4*)(out + (size_t)bc * NN);
    for (int i = tid; i < NN / 4; i += 256) {
        float4 v = row[i];
        v.x *= s; v.y *= s; v.z *= s; v.w *= s;
        row[i] = v;
    }
}

// ---------------- launch ----------------
extern "C" void kernel_launch(void* const* d_in, const int* in_sizes, int n_in,
                              void* d_out, int out_size)
{
    const float* x     = (const float*)d_in[0];
    const float* wq    = (const float*)d_in[1];
    const float* bq    = (const float*)d_in[2];
    const float* wk    = (const float*)d_in[3];
    const float* bk    = (const float*)d_in[4];
    const float* wv    = (const float*)d_in[5];
    const float* bv    = (const float*)d_in[6];
    const float* ca_w1 = (const float*)d_in[7];
    const float* ca_w2 = (const float*)d_in[8];
    float* out = (float*)d_out;

    cudaFuncSetAttribute(attn_mma_kernel, cudaFuncAttributeMaxDynamicSharedMemorySize, SMEM_BYTES);

    init_kernel<<<1, 256>>>();
    qkv_kernel<<<dim3(NN / 256, BB), 256>>>(x, wq, bq, wk, bk, wv, bv);
    vsum_kernel<<<BB * CC, 256>>>();
    attn_mma_kernel<<<dim3(NN / TN, BB), 256, SMEM_BYTES>>>(x, out);
    apply_scale_kernel<<<BB * CC, 256>>>(out, ca_w1, ca_w2);
}